// round 2
// baseline (speedup 1.0000x reference)
#include <cuda_runtime.h>
#include <cstdint>

#define COLS      16384
#define KSEL      64
#define NTHREADS  512
#define GPT       (COLS / (NTHREADS * 4))   // 8 float4-groups per thread
#define CAP       2048

// Monotonic uint key for float ordering (no NaNs expected in data).
__device__ __forceinline__ unsigned fkey(float f) {
    unsigned u = __float_as_uint(f);
    return u ^ ((unsigned)((int)u >> 31) | 0x80000000u);
}

// Inverse of fkey for the pivot; map NaN-encoding keys to +/-inf so that
// float comparisons remain consistent with key-space counting.
__device__ __forceinline__ float key_to_pivot(unsigned k) {
    unsigned bits = (k & 0x80000000u) ? (k & 0x7FFFFFFFu) : ~k;
    float f = __uint_as_float(bits);
    if (f != f) {
        f = (k & 0x80000000u) ? __uint_as_float(0x7F800000u)   // +inf
                              : __uint_as_float(0xFF800000u);  // -inf
    }
    return f;
}

__global__ void __launch_bounds__(NTHREADS)
sparsify_topk_kernel(const float* __restrict__ x, float* __restrict__ out)
{
    __shared__ unsigned s_key[CAP];
    __shared__ int      s_idx[CAP];
    __shared__ int      s_cnt;
    __shared__ unsigned s_pk, s_lo, s_hi, s_tkey;
    __shared__ int      s_status;   // 0 retry, 2 final-pass(T==new pivot), 3 done

    const int    tid = threadIdx.x;
    const size_t row = blockIdx.x;
    const float4* __restrict__ vin  = (const float4*)(x   + row * (size_t)COLS);
    float4*       __restrict__ vout = (float4*)      (out + row * (size_t)COLS);

    if (tid == 0) {
        s_pk = fkey(2.4f);      // initial pivot: E[candidates] ~ 135 for N(0,1)
        s_lo = 0u;              // invariant: count(key >= s_lo) >= KSEL
        s_hi = 0xFFFFFFFFu;
        s_status = 0;
    }
    __syncthreads();

    bool finalPass = false;

    for (;;) {
        float pivotf = key_to_pivot(s_pk);
        if (tid == 0) s_cnt = 0;
        __syncthreads();

        #pragma unroll
        for (int it = 0; it < GPT; ++it) {
            int g = tid + it * NTHREADS;
            float4 v = vin[g];
            float m = fmaxf(fmaxf(v.x, v.y), fmaxf(v.z, v.w));
            if (m >= pivotf) {
                // rare path: ~135 groups out of 4096 per row
                float4 o;
                o.x = (v.x >= pivotf) ? v.x : 0.0f;
                o.y = (v.y >= pivotf) ? v.y : 0.0f;
                o.z = (v.z >= pivotf) ? v.z : 0.0f;
                o.w = (v.w >= pivotf) ? v.w : 0.0f;
                vout[g] = o;
                int base = g * 4;
                if (v.x >= pivotf) { int p = atomicAdd(&s_cnt, 1); if (p < CAP) { s_key[p] = fkey(v.x); s_idx[p] = base + 0; } }
                if (v.y >= pivotf) { int p = atomicAdd(&s_cnt, 1); if (p < CAP) { s_key[p] = fkey(v.y); s_idx[p] = base + 1; } }
                if (v.z >= pivotf) { int p = atomicAdd(&s_cnt, 1); if (p < CAP) { s_key[p] = fkey(v.z); s_idx[p] = base + 2; } }
                if (v.w >= pivotf) { int p = atomicAdd(&s_cnt, 1); if (p < CAP) { s_key[p] = fkey(v.w); s_idx[p] = base + 3; } }
            } else {
                vout[g] = make_float4(0.f, 0.f, 0.f, 0.f);
            }
        }
        __syncthreads();

        if (finalPass) return;       // out already exact (T == pivot), no fixup

        int cc = s_cnt;              // uniform: read after barrier
        if (cc >= KSEL && cc <= CAP) break;   // go select exact threshold

        // Bisection retry in key space (essentially never taken on this input)
        if (tid == 0) {
            if (cc < KSEL) {
                s_hi = s_pk;
                unsigned step = (s_pk - s_lo) >> 1;
                if (step == 0) { s_pk = s_lo; s_status = 2; }  // T == s_lo exactly
                else           { s_pk -= step; s_status = 0; }
            } else { // cc > CAP
                s_lo = s_pk;
                unsigned step = (s_hi - s_pk) >> 1;
                if (step == 0) { s_status = 3; }  // T == s_pk; out already correct
                else           { s_pk += step; s_status = 0; }
            }
        }
        __syncthreads();
        int st = s_status;           // uniform
        if (st == 3) return;
        if (st == 2) finalPass = true;
    }

    // --- exact selection: 64th largest key among c candidates (warp 0) ---
    int c = s_cnt;   // 64 <= c <= CAP
    if (tid < 32) {
        unsigned cur = 0;
        for (int b = 31; b >= 0; --b) {
            unsigned t = cur | (1u << b);
            int cnt = 0;
            for (int i = tid; i < c; i += 32)
                cnt += (s_key[i] >= t) ? 1 : 0;
            cnt = __reduce_add_sync(0xFFFFFFFFu, cnt);
            if (cnt >= KSEL) cur = t;
        }
        if (tid == 0) s_tkey = cur;
    }
    __syncthreads();

    // --- fixup: zero candidates strictly below the exact threshold ---
    unsigned T = s_tkey;
    float* orow = out + row * (size_t)COLS;
    for (int i = tid; i < c; i += NTHREADS) {
        if (s_key[i] < T) orow[s_idx[i]] = 0.0f;
    }
}

extern "C" void kernel_launch(void* const* d_in, const int* in_sizes, int n_in,
                              void* d_out, int out_size) {
    const float* x = (const float*)d_in[0];
    float* out = (float*)d_out;
    int rows = in_sizes[0] / COLS;
    sparsify_topk_kernel<<<rows, NTHREADS>>>(x, out);
}